// round 7
// baseline (speedup 1.0000x reference)
#include <cuda_runtime.h>
#include <math.h>

#define TPB     256
#define JN      128
#define MP      128
#define PSPLIT  4                 // patch quarters per point-block
#define MH      (MP / PSPLIT)     // 32 patches per build block
#define CAP     4096              // per-patch segment capacity (max real ~1300)
#define SQCAP   1024              // smem queue cap per build block (expected ~165)
#define CHY     3                 // process: y-blocks per patch (2*TPB*CHY = 1536 slots)

// scratch: static __device__ arrays (zero-initialized at module load)
__device__ int    g_cnt[MP];
__device__ int    g_idx[MP * CAP];
__device__ float2 g_std[MP * CAP];

__device__ __forceinline__ float frcp(float x) {
    float r; asm("rcp.approx.f32 %0, %1;" : "=f"(r) : "f"(x)); return r;
}
__device__ __forceinline__ float fex2(float x) {
    float r; asm("ex2.approx.f32 %0, %1;" : "=f"(r) : "f"(x)); return r;
}

// ---------------------------------------------------------------------------
// build: grid (N/TPB, PSPLIT). 256 points vs 32 patches per block.
// Warp-aggregated compaction: one ballot per patch-iteration; the elected
// leader does the (sqpos, scnt) smem atomics for the whole warp; lanes get
// slots from popc-prefix + shfl. Then one wave of 32 global atomicAdds
// reserves contiguous per-patch space, then scatter-copy.
// |p-c| <= 0.25  <=>  |std| <= 1 exactly (x4 exact in fp32).
// ---------------------------------------------------------------------------
__global__ void __launch_bounds__(TPB)
rf_build_kernel(const float2* __restrict__ p2, const float2* __restrict__ cs2,
                float* __restrict__ out, int N)
{
    __shared__ float2 sc[MH];
    __shared__ int    scnt[MH];
    __shared__ int    sbase[MH];
    __shared__ int    sqpos;
    __shared__ int    qkey[SQCAP];   // (mm << 16) | patch-slot
    __shared__ int    qn[SQCAP];
    __shared__ float2 qs[SQCAP];

    const int tid  = threadIdx.x;
    const int lane = tid & 31;
    const int m0   = blockIdx.y * MH;

    for (int i = tid; i < MH; i += TPB) { sc[i] = cs2[m0 + i]; scnt[i] = 0; }
    if (tid == 0) sqpos = 0;
    __syncthreads();

    const int  n     = blockIdx.x * TPB + tid;
    const bool valid = (n < N);
    float2 pv = make_float2(1e30f, 1e30f);     // never hits
    if (valid) {
        if (blockIdx.y == 0) out[n] = 0.0f;    // zero out (process runs later)
        pv = p2[n];
    }

    // phase 1: scan + warp-aggregated smem staging
    #pragma unroll 4
    for (int mm = 0; mm < MH; mm++) {
        const float2 c = sc[mm];
        const float d0 = pv.x - c.x;
        const float d1 = pv.y - c.y;
        const bool hit = (fabsf(d0) <= 0.25f) && (fabsf(d1) <= 0.25f);
        const unsigned mask = __ballot_sync(0xFFFFFFFFu, hit);
        if (mask) {
            const int cnt    = __popc(mask);
            const int leader = __ffs(mask) - 1;
            int wq = 0, wb = 0;
            if (lane == leader) {
                wq = atomicAdd(&sqpos, cnt);
                wb = atomicAdd(&scnt[mm], cnt);
            }
            wq = __shfl_sync(0xFFFFFFFFu, wq, leader);
            wb = __shfl_sync(0xFFFFFFFFu, wb, leader);
            if (hit) {
                const int pre = __popc(mask & ((1u << lane) - 1));
                const int pos = wq + pre;
                if (pos < SQCAP) {
                    qkey[pos] = (mm << 16) | (wb + pre);
                    qn[pos]   = n;
                    qs[pos]   = make_float2(d0 * 4.0f, d1 * 4.0f);
                }
            }
        }
    }
    __syncthreads();

    // phase 2: one parallel wave of global reservations
    if (tid < MH) sbase[tid] = atomicAdd(&g_cnt[m0 + tid], scnt[tid]);
    __syncthreads();

    // phase 3: scatter smem queue -> per-patch contiguous gmem segments
    const int qtot = min(sqpos, SQCAP);
    for (int i = tid; i < qtot; i += TPB) {
        const int key  = qkey[i];
        const int mm   = key >> 16;
        const int gpos = sbase[mm] + (key & 0xFFFF);
        if (gpos < CAP) {
            const int at = (m0 + mm) * CAP + gpos;
            g_idx[at] = qn[i];
            g_std[at] = qs[i];
        }
    }
}

// ---------------------------------------------------------------------------
// process: block = (patch m, chunk y); 2 entries per thread so each broadcast
// coefficient LDS feeds two FMA streams. Coefficients prescaled by 2*log2(e)
// so tanh(a) = 1 - 2*rcp(ex2(a') + 1) costs 1 EX2 per j; one RCP is shared
// across a j-pair via the paired-reciprocal identity. rel err ~1e-7.
// ---------------------------------------------------------------------------
__global__ void __launch_bounds__(TPB)
rf_process_kernel(const float* __restrict__ W, const float* __restrict__ b,
                  const float* __restrict__ um, float* __restrict__ out)
{
    const int m   = blockIdx.x;
    const int cnt = min(g_cnt[m], CAP);
    if (cnt <= blockIdx.y * (2 * TPB)) return;     // uniform per block

    __shared__ float4 sC[JN];
    const float K = 2.8853900817779268f;           // 2/ln(2)
    for (int j = threadIdx.x; j < JN; j += TPB) {
        sC[j] = make_float4(W[m * (2 * JN) + j] * K,        // W[m,0,j]*K
                            W[m * (2 * JN) + JN + j] * K,   // W[m,1,j]*K
                            b[m * JN + j] * K,
                            um[m * JN + j]);
    }
    __syncthreads();

    const int*    segN = g_idx + m * CAP;
    const float2* segS = g_std + m * CAP;

    for (int i0 = blockIdx.y * (2 * TPB) + threadIdx.x; i0 < cnt;
         i0 += 2 * TPB * CHY) {
        const int i1 = i0 + TPB;
        const bool has1 = (i1 < cnt);
        const int    nA = segN[i0];
        const float2 sA = segS[i0];
        int    nB = 0;
        float2 sB = make_float2(0.f, 0.f);
        if (has1) { nB = segN[i1]; sB = segS[i1]; }

        float accA = 0.f, accB = 0.f;
        #pragma unroll 8
        for (int j = 0; j < JN; j += 2) {
            const float4 ca = sC[j];
            const float4 cb = sC[j + 1];
            // entry A
            {
                float a0 = fmaf(sA.x, ca.x, fmaf(sA.y, ca.y, ca.z));
                float a1 = fmaf(sA.x, cb.x, fmaf(sA.y, cb.y, cb.z));
                float x0 = fex2(a0) + 1.0f;
                float x1 = fex2(a1) + 1.0f;
                float r  = frcp(x0 * x1);
                float t0 = fmaf(-2.0f * x1, r, 1.0f);
                float t1 = fmaf(-2.0f * x0, r, 1.0f);
                accA = fmaf(t0, ca.w, accA);
                accA = fmaf(t1, cb.w, accA);
            }
            // entry B
            {
                float a0 = fmaf(sB.x, ca.x, fmaf(sB.y, ca.y, ca.z));
                float a1 = fmaf(sB.x, cb.x, fmaf(sB.y, cb.y, cb.z));
                float x0 = fex2(a0) + 1.0f;
                float x1 = fex2(a1) + 1.0f;
                float r  = frcp(x0 * x1);
                float t0 = fmaf(-2.0f * x1, r, 1.0f);
                float t1 = fmaf(-2.0f * x0, r, 1.0f);
                accB = fmaf(t0, ca.w, accB);
                accB = fmaf(t1, cb.w, accB);
            }
        }
        atomicAdd(&out[nA], accA);
        if (has1) atomicAdd(&out[nB], accB);
    }
}

// ---------------------------------------------------------------------------
// reset: restore counter zero-invariant for the next graph replay
// ---------------------------------------------------------------------------
__global__ void rf_reset_kernel() {
    if (threadIdx.x < MP) g_cnt[threadIdx.x] = 0;
}

// ---------------------------------------------------------------------------
// inputs (metadata order): p[N,2] f32, cs[128,2] f32, W[128,2,128] f32,
//                          b[128,128] f32, um[128,128] f32 ; out [N,1] f32
// ---------------------------------------------------------------------------
extern "C" void kernel_launch(void* const* d_in, const int* in_sizes, int n_in,
                              void* d_out, int out_size)
{
    const float* p  = (const float*)d_in[0];
    const float* cs = (const float*)d_in[1];
    const float* W  = (const float*)d_in[2];
    const float* b  = (const float*)d_in[3];
    const float* um = (const float*)d_in[4];
    float* out = (float*)d_out;

    const int N = in_sizes[0] / 2;   // 32768

    dim3 bgrid((N + TPB - 1) / TPB, PSPLIT);
    rf_build_kernel<<<bgrid, TPB>>>((const float2*)p, (const float2*)cs, out, N);

    dim3 pgrid(MP, CHY);
    rf_process_kernel<<<pgrid, TPB>>>(W, b, um, out);

    rf_reset_kernel<<<1, MP>>>();
}

// round 8
// speedup vs baseline: 1.0020x; 1.0020x over previous
#include <cuda_runtime.h>
#include <math.h>

#define TPB_B   512               // build block
#define TPB_P   256               // process block
#define JN      128
#define MP      128
#define GRID    32                // 32x32 cells of size 0.25 over [-4,4]
#define NCELL   (GRID * GRID)
#define CCAP    128               // per-cell patch-list capacity (exact-safe)
#define CAP     4096              // per-patch segment capacity (max real ~1300)
#define SQCAP   2048              // smem queue per build block (expected ~1310)
#define CHY     6                 // process chunks per patch

// scratch: static __device__ arrays (zero-initialized at module load)
__device__ int    g_cellCnt[NCELL];
__device__ int    g_cellList[NCELL * CCAP];
__device__ int    g_cnt[MP];
__device__ int    g_idx[MP * CAP];
__device__ float2 g_std[MP * CAP];

__device__ __forceinline__ int cell_of(float v) {
    int i = (int)floorf((v + 4.0f) * 4.0f);
    return min(GRID - 1, max(0, i));
}

// ---------------------------------------------------------------------------
// bin: 1 block. Zeroes g_cellCnt and g_cnt (per-call reset), then registers
// each patch in every cell its (margin-padded) 0.5-box overlaps. The 1e-5
// margin guarantees no fp false-negative at cell boundaries; the exact test
// in build decides membership, so extra cells cost only a wasted test.
// ---------------------------------------------------------------------------
__global__ void rf_bin_kernel(const float2* __restrict__ cs2)
{
    const int t = threadIdx.x;
    if (t < NCELL) g_cellCnt[t] = 0;
    if (t < MP)    g_cnt[t]     = 0;
    __syncthreads();

    if (t < MP) {
        const float2 c = cs2[t];
        const float R = 0.25001f;
        const int ix0 = cell_of(c.x - R), ix1 = cell_of(c.x + R);
        const int iy0 = cell_of(c.y - R), iy1 = cell_of(c.y + R);
        for (int iy = iy0; iy <= iy1; iy++)
            for (int ix = ix0; ix <= ix1; ix++) {
                const int cell = iy * GRID + ix;
                const int s = atomicAdd(&g_cellCnt[cell], 1);
                if (s < CCAP) g_cellList[cell * CCAP + s] = t;
            }
    }
}

// ---------------------------------------------------------------------------
// build: 64 blocks x 512. Per point: zero out[n], find cell, test only the
// ~5.6 candidate patches in that cell's list (vs all 128). Hits go into a
// block smem queue (one warp-aggregated atomic per iteration). Post-passes:
// smem histogram -> one 128-wide global reservation wave -> cursor scatter
// into contiguous per-patch gmem segments.
// |p-c| <= 0.25  <=>  |std| <= 1 exactly (x4 exact in fp32).
// ---------------------------------------------------------------------------
__global__ void __launch_bounds__(TPB_B)
rf_build_kernel(const float2* __restrict__ p2, const float2* __restrict__ cs2,
                float* __restrict__ out, int N)
{
    __shared__ float2 scs[MP];
    __shared__ int    scnt[MP];
    __shared__ int    sbase[MP];
    __shared__ int    sqpos;
    __shared__ int    qmn[SQCAP];     // (m << 16) | n
    __shared__ float2 qs[SQCAP];

    const int tid  = threadIdx.x;
    const int lane = tid & 31;

    for (int i = tid; i < MP; i += TPB_B) { scs[i] = cs2[i]; scnt[i] = 0; }
    if (tid == 0) sqpos = 0;
    __syncthreads();

    const int n = blockIdx.x * TPB_B + tid;
    float2 pv = make_float2(1e30f, 1e30f);
    int cell = 0, k = 0;
    if (n < N) {
        out[n] = 0.0f;                 // zero output (process runs later)
        pv = p2[n];
        cell = cell_of(pv.y) * GRID + cell_of(pv.x);
        k = min(g_cellCnt[cell], CCAP);
    }
    const int kmax = __reduce_max_sync(0xFFFFFFFFu, k);

    // phase 1: scan candidates + warp-aggregated smem staging
    for (int t = 0; t < kmax; t++) {
        const bool cand = (t < k);
        const int  m = cand ? g_cellList[cell * CCAP + t] : 0;
        const float2 c = scs[m];
        const float d0 = pv.x - c.x;
        const float d1 = pv.y - c.y;
        const bool hit = cand && (fabsf(d0) <= 0.25f) && (fabsf(d1) <= 0.25f);
        const unsigned mask = __ballot_sync(0xFFFFFFFFu, hit);
        if (mask) {
            const int cnt    = __popc(mask);
            const int leader = __ffs(mask) - 1;
            int wq = 0;
            if (lane == leader) wq = atomicAdd(&sqpos, cnt);
            wq = __shfl_sync(0xFFFFFFFFu, wq, leader);
            if (hit) {
                const int pos = wq + __popc(mask & ((1u << lane) - 1));
                if (pos < SQCAP) {
                    qmn[pos] = (m << 16) | n;
                    qs[pos]  = make_float2(d0 * 4.0f, d1 * 4.0f);
                }
            }
        }
    }
    __syncthreads();
    const int qtot = min(sqpos, SQCAP);

    // phase 2: per-patch histogram (spread-address smem atomics)
    for (int i = tid; i < qtot; i += TPB_B)
        atomicAdd(&scnt[qmn[i] >> 16], 1);
    __syncthreads();

    // phase 3: one wave of global reservations; sbase becomes scatter cursor
    if (tid < MP) sbase[tid] = atomicAdd(&g_cnt[tid], scnt[tid]);
    __syncthreads();

    // phase 4: scatter queue -> contiguous per-patch segments
    for (int i = tid; i < qtot; i += TPB_B) {
        const int key = qmn[i];
        const int m   = key >> 16;
        const int g   = atomicAdd(&sbase[m], 1);
        if (g < CAP) {
            const int at = m * CAP + g;
            g_idx[at] = key & 0xFFFF;
            g_std[at] = qs[i];
        }
    }
}

// ---------------------------------------------------------------------------
// process (R5 version, measured-good): block = (patch m, chunk y). Dense
// warps over the contiguous segment; coefficients broadcast from smem;
// tanh = 1 - 2/(exp(2x)+1) (MUFU.EX2 + MUFU.RCP, ~1e-7 rel).
// ---------------------------------------------------------------------------
__global__ void __launch_bounds__(TPB_P)
rf_process_kernel(const float* __restrict__ W, const float* __restrict__ b,
                  const float* __restrict__ um, float* __restrict__ out)
{
    const int m   = blockIdx.x;
    const int cnt = min(g_cnt[m], CAP);
    if (cnt <= blockIdx.y * TPB_P) return;        // uniform per block

    __shared__ float4 sC[JN];
    for (int j = threadIdx.x; j < JN; j += TPB_P) {
        sC[j] = make_float4(W[m * (2 * JN) + j],        // W[m,0,j]
                            W[m * (2 * JN) + JN + j],   // W[m,1,j]
                            b[m * JN + j],
                            um[m * JN + j]);
    }
    __syncthreads();

    const int*    segN = g_idx + m * CAP;
    const float2* segS = g_std + m * CAP;

    for (int i = blockIdx.y * TPB_P + threadIdx.x; i < cnt; i += TPB_P * CHY) {
        const int    n = segN[i];
        const float2 s = segS[i];
        float acc0 = 0.0f, acc1 = 0.0f;
        #pragma unroll 8
        for (int j = 0; j < JN; j += 2) {
            const float4 ca = sC[j];
            const float4 cb = sC[j + 1];
            float a0 = fmaf(s.x, ca.x, fmaf(s.y, ca.y, ca.z));
            float a1 = fmaf(s.x, cb.x, fmaf(s.y, cb.y, cb.z));
            float e0 = __expf(2.0f * a0);
            float e1 = __expf(2.0f * a1);
            float t0 = 1.0f - __fdividef(2.0f, e0 + 1.0f);
            float t1 = 1.0f - __fdividef(2.0f, e1 + 1.0f);
            acc0 = fmaf(t0, ca.w, acc0);
            acc1 = fmaf(t1, cb.w, acc1);
        }
        atomicAdd(&out[n], acc0 + acc1);
    }
}

// ---------------------------------------------------------------------------
// inputs (metadata order): p[N,2] f32, cs[128,2] f32, W[128,2,128] f32,
//                          b[128,128] f32, um[128,128] f32 ; out [N,1] f32
// ---------------------------------------------------------------------------
extern "C" void kernel_launch(void* const* d_in, const int* in_sizes, int n_in,
                              void* d_out, int out_size)
{
    const float* p  = (const float*)d_in[0];
    const float* cs = (const float*)d_in[1];
    const float* W  = (const float*)d_in[2];
    const float* b  = (const float*)d_in[3];
    const float* um = (const float*)d_in[4];
    float* out = (float*)d_out;

    const int N = in_sizes[0] / 2;   // 32768

    rf_bin_kernel<<<1, 1024>>>((const float2*)cs);

    rf_build_kernel<<<(N + TPB_B - 1) / TPB_B, TPB_B>>>(
        (const float2*)p, (const float2*)cs, out, N);

    dim3 pgrid(MP, CHY);
    rf_process_kernel<<<pgrid, TPB_P>>>(W, b, um, out);
}

// round 9
// speedup vs baseline: 1.2069x; 1.2045x over previous
#include <cuda_runtime.h>
#include <math.h>

#define TPB_B   256               // build block
#define TPB_P   256               // process block
#define JN      128
#define MP      128
#define GRID    32                // 32x32 cells of size 0.25 over [-4,4]
#define NCELL   (GRID * GRID)
#define CCAP    128               // per-cell patch-list capacity (128 patches max)
#define CAP     4096              // per-patch segment capacity (max real ~1300)
#define SQCAP   1536              // smem queue per build block (expected ~655)
#define CHY     11                // process y-blocks per patch (128 entries each)

// scratch: static __device__ arrays (zero-initialized at module load)
__device__ int    g_cellCnt[NCELL];
__device__ int    g_cellList[NCELL * CCAP];
__device__ int    g_cnt[MP];
__device__ int    g_idx[MP * CAP];
__device__ float2 g_std[MP * CAP];

__device__ __forceinline__ int cell_clamp(int i) {
    return min(GRID - 1, max(0, i));
}
__device__ __forceinline__ int cell_of(float v) {
    return cell_clamp((int)floorf((v + 4.0f) * 4.0f));
}

// ---------------------------------------------------------------------------
// bin: 8 blocks x 128. Thread = one cell; scans all 128 centers from smem and
// writes its candidate list sequentially -> NO atomics, no serial chains.
// Cell [x0,x1]x[y0,y1]; patch m is a candidate iff its (margin-padded)
// 0.5-box overlaps the cell. Margin 1e-5 kills fp edge false-negatives; the
// exact |d|<=0.25 test in build decides membership. Also resets g_cnt.
// ---------------------------------------------------------------------------
__global__ void __launch_bounds__(128)
rf_bin_kernel(const float2* __restrict__ cs2)
{
    __shared__ float2 scs[MP];
    for (int i = threadIdx.x; i < MP; i += 128) scs[i] = cs2[i];
    __syncthreads();

    const int cell = blockIdx.x * 128 + threadIdx.x;   // 0..1023
    if (blockIdx.x == 0 && threadIdx.x < MP) g_cnt[threadIdx.x] = 0;

    const int ix = cell & (GRID - 1);
    const int iy = cell >> 5;
    const float x0 = -4.0f + 0.25f * ix, x1 = x0 + 0.25f;
    const float y0 = -4.0f + 0.25f * iy, y1 = y0 + 0.25f;
    const float R = 0.25001f;

    int cnt = 0;
    int* list = g_cellList + cell * CCAP;
    #pragma unroll 4
    for (int m = 0; m < MP; m++) {
        const float2 c = scs[m];
        // overlap: also extend edge cells to catch clamped out-of-range points
        const bool ovx = (c.x - R <= x1 || ix == GRID - 1) &&
                         (c.x + R >= x0 || ix == 0);
        const bool ovy = (c.y - R <= y1 || iy == GRID - 1) &&
                         (c.y + R >= y0 || iy == 0);
        if (ovx && ovy) list[cnt++] = m;
    }
    g_cellCnt[cell] = cnt;
}

// ---------------------------------------------------------------------------
// build: 128 blocks x 256. Per point: zero out[n], find cell, test only the
// ~5.6 candidates in that cell's list. Hits -> block smem queue (one
// warp-aggregated atomic per iteration). Post: smem histogram -> one 128-wide
// global reservation wave -> cursor scatter into contiguous segments.
// |p-c| <= 0.25  <=>  |std| <= 1 exactly (x4 exact in fp32).
// ---------------------------------------------------------------------------
__global__ void __launch_bounds__(TPB_B)
rf_build_kernel(const float2* __restrict__ p2, const float2* __restrict__ cs2,
                float* __restrict__ out, int N)
{
    __shared__ float2 scs[MP];
    __shared__ int    scnt[MP];
    __shared__ int    sbase[MP];
    __shared__ int    sqpos;
    __shared__ int    qmn[SQCAP];     // (m << 16) | n
    __shared__ float2 qs[SQCAP];

    const int tid  = threadIdx.x;
    const int lane = tid & 31;

    for (int i = tid; i < MP; i += TPB_B) { scs[i] = cs2[i]; scnt[i] = 0; }
    if (tid == 0) sqpos = 0;
    __syncthreads();

    const int n = blockIdx.x * TPB_B + tid;
    float2 pv = make_float2(1e30f, 1e30f);
    int cell = 0, k = 0;
    if (n < N) {
        out[n] = 0.0f;                 // zero output (process runs later)
        pv = p2[n];
        cell = (cell_of(pv.y) << 5) | cell_of(pv.x);
        k = g_cellCnt[cell];
    }
    const int kmax = __reduce_max_sync(0xFFFFFFFFu, k);

    // phase 1: scan candidates + warp-aggregated smem staging
    for (int t = 0; t < kmax; t++) {
        const bool cand = (t < k);
        const int  m = cand ? g_cellList[cell * CCAP + t] : 0;
        const float2 c = scs[m];
        const float d0 = pv.x - c.x;
        const float d1 = pv.y - c.y;
        const bool hit = cand && (fabsf(d0) <= 0.25f) && (fabsf(d1) <= 0.25f);
        const unsigned mask = __ballot_sync(0xFFFFFFFFu, hit);
        if (mask) {
            const int cnt    = __popc(mask);
            const int leader = __ffs(mask) - 1;
            int wq = 0;
            if (lane == leader) wq = atomicAdd(&sqpos, cnt);
            wq = __shfl_sync(0xFFFFFFFFu, wq, leader);
            if (hit) {
                const int pos = wq + __popc(mask & ((1u << lane) - 1));
                if (pos < SQCAP) {
                    qmn[pos] = (m << 16) | n;
                    qs[pos]  = make_float2(d0 * 4.0f, d1 * 4.0f);
                }
            }
        }
    }
    __syncthreads();
    const int qtot = min(sqpos, SQCAP);

    // phase 2: per-patch histogram (spread-address smem atomics)
    for (int i = tid; i < qtot; i += TPB_B)
        atomicAdd(&scnt[qmn[i] >> 16], 1);
    __syncthreads();

    // phase 3: one wave of global reservations; sbase becomes scatter cursor
    if (tid < MP) sbase[tid] = atomicAdd(&g_cnt[tid], scnt[tid]);
    __syncthreads();

    // phase 4: scatter queue -> contiguous per-patch segments
    for (int i = tid; i < qtot; i += TPB_B) {
        const int key = qmn[i];
        const int m   = key >> 16;
        const int g   = atomicAdd(&sbase[m], 1);
        if (g < CAP) {
            const int at = m * CAP + g;
            g_idx[at] = key & 0xFFFF;
            g_std[at] = qs[i];
        }
    }
}

// ---------------------------------------------------------------------------
// process: split-j — 2 threads per entry, each owns 64 of the 128 j's
// (halves the serial FMA->EX2->RCP chain per thread), combined by one
// shfl_xor. Coefficients broadcast from smem; tanh = 1 - 2/(exp(2x)+1)
// (MUFU.EX2 + MUFU.RCP, ~1e-7 rel). Warp-uniform while(ballot) loop keeps
// the shfl legal at segment edges.
// ---------------------------------------------------------------------------
__global__ void __launch_bounds__(TPB_P)
rf_process_kernel(const float* __restrict__ W, const float* __restrict__ b,
                  const float* __restrict__ um, float* __restrict__ out)
{
    const int m   = blockIdx.x;
    const int cnt = min(g_cnt[m], CAP);
    const int EPB = TPB_P / 2;                    // entries per block-pass
    if (cnt <= blockIdx.y * EPB) return;          // uniform per block

    __shared__ float4 sC[JN];
    for (int j = threadIdx.x; j < JN; j += TPB_P) {
        sC[j] = make_float4(W[m * (2 * JN) + j],        // W[m,0,j]
                            W[m * (2 * JN) + JN + j],   // W[m,1,j]
                            b[m * JN + j],
                            um[m * JN + j]);
    }
    __syncthreads();

    const int*    segN = g_idx + m * CAP;
    const float2* segS = g_std + m * CAP;
    const int jbase = (threadIdx.x & 1) * (JN / 2);   // 0 or 64

    int i = blockIdx.y * EPB + (threadIdx.x >> 1);
    while (__ballot_sync(0xFFFFFFFFu, i < cnt)) {
        const bool valid = (i < cnt);
        int    n = 0;
        float2 s = make_float2(0.0f, 0.0f);
        if (valid) { n = segN[i]; s = segS[i]; }

        float acc0 = 0.0f, acc1 = 0.0f;
        #pragma unroll 8
        for (int jj = 0; jj < JN / 2; jj += 2) {
            const float4 ca = sC[jbase + jj];
            const float4 cb = sC[jbase + jj + 1];
            float a0 = fmaf(s.x, ca.x, fmaf(s.y, ca.y, ca.z));
            float a1 = fmaf(s.x, cb.x, fmaf(s.y, cb.y, cb.z));
            float e0 = __expf(2.0f * a0);
            float e1 = __expf(2.0f * a1);
            float t0 = 1.0f - __fdividef(2.0f, e0 + 1.0f);
            float t1 = 1.0f - __fdividef(2.0f, e1 + 1.0f);
            acc0 = fmaf(t0, ca.w, acc0);
            acc1 = fmaf(t1, cb.w, acc1);
        }
        float acc = acc0 + acc1;
        acc += __shfl_xor_sync(0xFFFFFFFFu, acc, 1);  // combine j-halves
        if (valid && !(threadIdx.x & 1)) atomicAdd(&out[n], acc);
        i += EPB * CHY;
    }
}

// ---------------------------------------------------------------------------
// inputs (metadata order): p[N,2] f32, cs[128,2] f32, W[128,2,128] f32,
//                          b[128,128] f32, um[128,128] f32 ; out [N,1] f32
// ---------------------------------------------------------------------------
extern "C" void kernel_launch(void* const* d_in, const int* in_sizes, int n_in,
                              void* d_out, int out_size)
{
    const float* p  = (const float*)d_in[0];
    const float* cs = (const float*)d_in[1];
    const float* W  = (const float*)d_in[2];
    const float* b  = (const float*)d_in[3];
    const float* um = (const float*)d_in[4];
    float* out = (float*)d_out;

    const int N = in_sizes[0] / 2;   // 32768

    rf_bin_kernel<<<8, 128>>>((const float2*)cs);

    rf_build_kernel<<<(N + TPB_B - 1) / TPB_B, TPB_B>>>(
        (const float2*)p, (const float2*)cs, out, N);

    dim3 pgrid(MP, CHY);
    rf_process_kernel<<<pgrid, TPB_P>>>(W, b, um, out);
}

// round 11
// speedup vs baseline: 1.4401x; 1.1932x over previous
#include <cuda_runtime.h>
#include <math.h>

#define TPB_B   256               // build block
#define TPB_P   256               // process block
#define JN      128
#define MP      128
#define GRID    32                // 32x32 cells of size 0.25 over [-4,4]
#define NCELL   (GRID * GRID)
#define CCAP    128               // per-cell patch-list capacity (128 patches max)
#define CAP     4096              // per-patch segment capacity (max real ~1300)
#define SQCAP   1536              // smem queue per build block (expected ~655)
#define CHY     11                // process y-blocks per patch (128 entries each)

// scratch: static __device__ arrays (zero-initialized at module load)
__device__ int    g_cellCnt[NCELL];
__device__ int    g_cellList[NCELL * CCAP];
__device__ int    g_cnt[MP];
__device__ int    g_idx[MP * CAP];
__device__ float2 g_std[MP * CAP];

__device__ __forceinline__ int cell_clamp(int i) {
    return min(GRID - 1, max(0, i));
}
__device__ __forceinline__ int cell_of(float v) {
    return cell_clamp((int)floorf((v + 4.0f) * 4.0f));
}

// ---------------------------------------------------------------------------
// bin: WARP-PER-CELL. 64 blocks x 512 = 1024 warps = 1024 cells. Each lane
// tests 4 patches (m = r*32+lane); ballot + popc-prefix writes the compacted
// candidate list cooperatively — no atomics, no serial chains, full-chip
// spread. Margin 1e-5 kills fp edge false-negatives; edge cells extend
// outward to catch clamped out-of-range points; the exact |d|<=0.25 test in
// build decides membership. Also resets g_cnt.
// ---------------------------------------------------------------------------
__global__ void __launch_bounds__(512)
rf_bin_kernel(const float2* __restrict__ cs2)
{
    __shared__ float2 scs[MP];
    for (int i = threadIdx.x; i < MP; i += 512) scs[i] = cs2[i];
    __syncthreads();

    const int wid  = threadIdx.x >> 5;
    const int lane = threadIdx.x & 31;
    const int cell = blockIdx.x * 16 + wid;            // 0..1023
    if (blockIdx.x == 0 && threadIdx.x < MP) g_cnt[threadIdx.x] = 0;

    const int ix = cell & (GRID - 1);
    const int iy = cell >> 5;
    const float x0 = -4.0f + 0.25f * ix, x1 = x0 + 0.25f;
    const float y0 = -4.0f + 0.25f * iy, y1 = y0 + 0.25f;
    const float R = 0.25001f;

    int* list = g_cellList + cell * CCAP;
    int base = 0;
    #pragma unroll
    for (int r = 0; r < MP / 32; r++) {
        const int m = r * 32 + lane;
        const float2 c = scs[m];
        const bool ovx = (c.x - R <= x1 || ix == GRID - 1) &&
                         (c.x + R >= x0 || ix == 0);
        const bool ovy = (c.y - R <= y1 || iy == GRID - 1) &&
                         (c.y + R >= y0 || iy == 0);
        const bool cand = ovx && ovy;
        const unsigned mask = __ballot_sync(0xFFFFFFFFu, cand);
        if (cand) list[base + __popc(mask & ((1u << lane) - 1))] = m;
        base += __popc(mask);
    }
    if (lane == 0) g_cellCnt[cell] = base;
}

// ---------------------------------------------------------------------------
// build: 128 blocks x 256. Per point: zero out[n], find cell, test only the
// ~5.6 candidates in that cell's list. Hits -> block smem queue (one
// warp-aggregated atomic per iteration). Post: smem histogram -> one 128-wide
// global reservation wave -> cursor scatter into contiguous segments.
// |p-c| <= 0.25  <=>  |std| <= 1 exactly (x4 exact in fp32).
// ---------------------------------------------------------------------------
__global__ void __launch_bounds__(TPB_B)
rf_build_kernel(const float2* __restrict__ p2, const float2* __restrict__ cs2,
                float* __restrict__ out, int N)
{
    __shared__ float2 scs[MP];
    __shared__ int    scnt[MP];
    __shared__ int    sbase[MP];
    __shared__ int    sqpos;
    __shared__ int    qmn[SQCAP];     // (m << 16) | n
    __shared__ float2 qs[SQCAP];

    const int tid  = threadIdx.x;
    const int lane = tid & 31;

    for (int i = tid; i < MP; i += TPB_B) { scs[i] = cs2[i]; scnt[i] = 0; }
    if (tid == 0) sqpos = 0;
    __syncthreads();

    const int n = blockIdx.x * TPB_B + tid;
    float2 pv = make_float2(1e30f, 1e30f);
    int cell = 0, k = 0;
    if (n < N) {
        out[n] = 0.0f;                 // zero output (process runs later)
        pv = p2[n];
        cell = (cell_of(pv.y) << 5) | cell_of(pv.x);
        k = g_cellCnt[cell];
    }
    const int kmax = __reduce_max_sync(0xFFFFFFFFu, k);

    // phase 1: scan candidates + warp-aggregated smem staging
    for (int t = 0; t < kmax; t++) {
        const bool cand = (t < k);
        const int  m = cand ? g_cellList[cell * CCAP + t] : 0;
        const float2 c = scs[m];
        const float d0 = pv.x - c.x;
        const float d1 = pv.y - c.y;
        const bool hit = cand && (fabsf(d0) <= 0.25f) && (fabsf(d1) <= 0.25f);
        const unsigned mask = __ballot_sync(0xFFFFFFFFu, hit);
        if (mask) {
            const int cnt    = __popc(mask);
            const int leader = __ffs(mask) - 1;
            int wq = 0;
            if (lane == leader) wq = atomicAdd(&sqpos, cnt);
            wq = __shfl_sync(0xFFFFFFFFu, wq, leader);
            if (hit) {
                const int pos = wq + __popc(mask & ((1u << lane) - 1));
                if (pos < SQCAP) {
                    qmn[pos] = (m << 16) | n;
                    qs[pos]  = make_float2(d0 * 4.0f, d1 * 4.0f);
                }
            }
        }
    }
    __syncthreads();
    const int qtot = min(sqpos, SQCAP);

    // phase 2: per-patch histogram (spread-address smem atomics)
    for (int i = tid; i < qtot; i += TPB_B)
        atomicAdd(&scnt[qmn[i] >> 16], 1);
    __syncthreads();

    // phase 3: one wave of global reservations; sbase becomes scatter cursor
    if (tid < MP) sbase[tid] = atomicAdd(&g_cnt[tid], scnt[tid]);
    __syncthreads();

    // phase 4: scatter queue -> contiguous per-patch segments
    for (int i = tid; i < qtot; i += TPB_B) {
        const int key = qmn[i];
        const int m   = key >> 16;
        const int g   = atomicAdd(&sbase[m], 1);
        if (g < CAP) {
            const int at = m * CAP + g;
            g_idx[at] = key & 0xFFFF;
            g_std[at] = qs[i];
        }
    }
}

// ---------------------------------------------------------------------------
// process: split-j — 2 threads per entry, each owns 64 of the 128 j's
// (halves the serial FMA->EX2->RCP chain per thread), combined by one
// shfl_xor. Coefficients broadcast from smem; tanh = 1 - 2/(exp(2x)+1)
// (MUFU.EX2 + MUFU.RCP, ~1e-7 rel). Warp-uniform while(ballot) loop keeps
// the shfl legal at segment edges.
// ---------------------------------------------------------------------------
__global__ void __launch_bounds__(TPB_P)
rf_process_kernel(const float* __restrict__ W, const float* __restrict__ b,
                  const float* __restrict__ um, float* __restrict__ out)
{
    const int m   = blockIdx.x;
    const int cnt = min(g_cnt[m], CAP);
    const int EPB = TPB_P / 2;                    // entries per block-pass
    if (cnt <= blockIdx.y * EPB) return;          // uniform per block

    __shared__ float4 sC[JN];
    for (int j = threadIdx.x; j < JN; j += TPB_P) {
        sC[j] = make_float4(W[m * (2 * JN) + j],        // W[m,0,j]
                            W[m * (2 * JN) + JN + j],   // W[m,1,j]
                            b[m * JN + j],
                            um[m * JN + j]);
    }
    __syncthreads();

    const int*    segN = g_idx + m * CAP;
    const float2* segS = g_std + m * CAP;
    const int jbase = (threadIdx.x & 1) * (JN / 2);   // 0 or 64

    int i = blockIdx.y * EPB + (threadIdx.x >> 1);
    while (__ballot_sync(0xFFFFFFFFu, i < cnt)) {
        const bool valid = (i < cnt);
        int    n = 0;
        float2 s = make_float2(0.0f, 0.0f);
        if (valid) { n = segN[i]; s = segS[i]; }

        float acc0 = 0.0f, acc1 = 0.0f;
        #pragma unroll 8
        for (int jj = 0; jj < JN / 2; jj += 2) {
            const float4 ca = sC[jbase + jj];
            const float4 cb = sC[jbase + jj + 1];
            float a0 = fmaf(s.x, ca.x, fmaf(s.y, ca.y, ca.z));
            float a1 = fmaf(s.x, cb.x, fmaf(s.y, cb.y, cb.z));
            float e0 = __expf(2.0f * a0);
            float e1 = __expf(2.0f * a1);
            float t0 = 1.0f - __fdividef(2.0f, e0 + 1.0f);
            float t1 = 1.0f - __fdividef(2.0f, e1 + 1.0f);
            acc0 = fmaf(t0, ca.w, acc0);
            acc1 = fmaf(t1, cb.w, acc1);
        }
        float acc = acc0 + acc1;
        acc += __shfl_xor_sync(0xFFFFFFFFu, acc, 1);  // combine j-halves
        if (valid && !(threadIdx.x & 1)) atomicAdd(&out[n], acc);
        i += EPB * CHY;
    }
}

// ---------------------------------------------------------------------------
// inputs (metadata order): p[N,2] f32, cs[128,2] f32, W[128,2,128] f32,
//                          b[128,128] f32, um[128,128] f32 ; out [N,1] f32
// ---------------------------------------------------------------------------
extern "C" void kernel_launch(void* const* d_in, const int* in_sizes, int n_in,
                              void* d_out, int out_size)
{
    const float* p  = (const float*)d_in[0];
    const float* cs = (const float*)d_in[1];
    const float* W  = (const float*)d_in[2];
    const float* b  = (const float*)d_in[3];
    const float* um = (const float*)d_in[4];
    float* out = (float*)d_out;

    const int N = in_sizes[0] / 2;   // 32768

    rf_bin_kernel<<<64, 512>>>((const float2*)cs);

    rf_build_kernel<<<(N + TPB_B - 1) / TPB_B, TPB_B>>>(
        (const float2*)p, (const float2*)cs, out, N);

    dim3 pgrid(MP, CHY);
    rf_process_kernel<<<pgrid, TPB_P>>>(W, b, um, out);
}